// round 1
// baseline (speedup 1.0000x reference)
#include <cuda_runtime.h>
#include <cuda_bf16.h>
#include <math.h>

// Problem constants
#define B_SZ 8
#define D_MODEL 2048
#define H_N 16
#define D_H 128
#define D_V 128
#define R_DIM 64
#define W_TOT 8192
#define NB 64
#define QKV_COLS (H_N * (2 * D_H + D_V))   // 6144
#define GAMMA 0.97f

// Output layout (concatenated flat float32):
// out (8,2048) | M_new (8,16,64,64) | z_new (8,16,64) | S_new (8,16,64,64)
#define OUT_OFF 0
#define M_OFF   (B_SZ * H_N * D_V)                       // 16384
#define Z_OFF   (M_OFF + B_SZ * H_N * R_DIM * R_DIM)     // 540672
#define S_OFF   (Z_OFF + B_SZ * H_N * R_DIM)             // 548864

// -------- scratch (device globals; no allocation allowed) --------
__device__ __align__(16) float g_h[B_SZ * D_MODEL];
__device__ __align__(16) float g_qkv[B_SZ * QKV_COLS];
__device__ __align__(16) float g_QL[B_SZ * H_N * R_DIM];
__device__ __align__(16) float g_KL[B_SZ * H_N * R_DIM];
__device__ __align__(16) float g_VL[B_SZ * H_N * R_DIM];
__device__ __align__(16) float g_attn[B_SZ * H_N * R_DIM];
__device__ int g_widx[B_SZ * W_TOT];
__device__ int g_wcnt[B_SZ];

// -------- helpers --------
__device__ __forceinline__ float softplusf(float x) {
    return fmaxf(x, 0.0f) + log1pf(expf(-fabsf(x)));
}
__device__ __forceinline__ float geluf(float x) {
    return 0.5f * x * (1.0f + erff(x * 0.70710678118654752440f));
}
__device__ __forceinline__ float sigmoidf(float x) {
    return 1.0f / (1.0f + expf(-x));
}

// ============================================================
// Kernel 1: LayerNorm   grid=8, block=256
// ============================================================
__global__ void k_ln(const float* __restrict__ x,
                     const float* __restrict__ g,
                     const float* __restrict__ bb) {
    int b = blockIdx.x, tid = threadIdx.x;
    __shared__ float red[256];
    const float* xr = x + b * D_MODEL;

    float s = 0.0f;
    for (int i = tid; i < D_MODEL; i += 256) s += xr[i];
    red[tid] = s; __syncthreads();
    for (int o = 128; o; o >>= 1) { if (tid < o) red[tid] += red[tid + o]; __syncthreads(); }
    float mu = red[0] * (1.0f / D_MODEL);
    __syncthreads();

    float v = 0.0f;
    for (int i = tid; i < D_MODEL; i += 256) { float d = xr[i] - mu; v += d * d; }
    red[tid] = v; __syncthreads();
    for (int o = 128; o; o >>= 1) { if (tid < o) red[tid] += red[tid + o]; __syncthreads(); }
    float inv = 1.0f / sqrtf(red[0] * (1.0f / D_MODEL) + 1e-5f);

    for (int i = tid; i < D_MODEL; i += 256)
        g_h[b * D_MODEL + i] = (xr[i] - mu) * inv * g[i] + bb[i];
}

// ============================================================
// Kernel 2: qkv = h @ W_qkv^T   grid=192, block=256
// Each warp: 4 output cols x 8 batches, float4, smem-tiled h.
// ============================================================
__global__ void __launch_bounds__(256) k_qkv(const float* __restrict__ W) {
    __shared__ float4 hs[B_SZ][128];   // 8 x 512 floats = 16 KB
    int tid = threadIdx.x;
    int warp = tid >> 5, lane = tid & 31;
    int colBase = blockIdx.x * 32 + warp * 4;

    float acc[4][8];
#pragma unroll
    for (int c = 0; c < 4; c++)
#pragma unroll
        for (int b = 0; b < 8; b++) acc[c][b] = 0.0f;

    for (int tile = 0; tile < 4; ++tile) {
        int k0 = tile * 512;
        for (int i = tid; i < 1024; i += 256) {
            int b = i >> 7, kk = i & 127;
            hs[b][kk] = *(const float4*)(&g_h[b * D_MODEL + k0 + kk * 4]);
        }
        __syncthreads();
#pragma unroll
        for (int kk = 0; kk < 4; ++kk) {
            int k4 = lane + kk * 32;
            float4 wv[4];
#pragma unroll
            for (int c = 0; c < 4; c++)
                wv[c] = *(const float4*)(&W[(size_t)(colBase + c) * D_MODEL + k0 + k4 * 4]);
#pragma unroll
            for (int b = 0; b < 8; b++) {
                float4 hv = hs[b][k4];
#pragma unroll
                for (int c = 0; c < 4; c++)
                    acc[c][b] += wv[c].x * hv.x + wv[c].y * hv.y + wv[c].z * hv.z + wv[c].w * hv.w;
            }
        }
        __syncthreads();
    }
#pragma unroll
    for (int c = 0; c < 4; c++)
#pragma unroll
        for (int b = 0; b < 8; b++) {
            float v = acc[c][b];
            for (int o = 16; o; o >>= 1) v += __shfl_down_sync(0xffffffffu, v, o);
            if (lane == 0) g_qkv[b * QKV_COLS + colBase + c] = v;
        }
}

// ============================================================
// Kernel 3: latent projections Q_L/K_L/V_L   grid=128, block=192
// ============================================================
__global__ void k_proj(const float* __restrict__ Eq,
                       const float* __restrict__ Ek,
                       const float* __restrict__ Ev) {
    int bh = blockIdx.x;
    int b = bh >> 4, h = bh & 15;
    int which = threadIdx.x / 64;
    int r = threadIdx.x & 63;

    const float* vec = g_qkv + b * QKV_COLS + h * 384 + which * 128;
    const float* E = (which == 0 ? Eq : (which == 1 ? Ek : Ev)) + (size_t)h * 128 * 64 + r;
    float acc = 0.0f;
#pragma unroll 8
    for (int d = 0; d < 128; ++d) acc += vec[d] * E[d * 64];

    float* dst = (which == 0 ? g_QL : (which == 1 ? g_KL : g_VL));
    dst[bh * 64 + r] = acc;
}

// ============================================================
// Kernel 4: routing scores + top-2 + ordered compaction   grid=8, block=256
// ============================================================
__global__ void k_route(const float* __restrict__ bm,
                        const int* __restrict__ bids,
                        const int* __restrict__ curp) {
    int b = blockIdx.x, tid = threadIdx.x;
    __shared__ float part[64][4];
    __shared__ float sarr[64];
    __shared__ int si1, si2;
    __shared__ int cnts[256];
    __shared__ int offs[257];

    int n = tid >> 2, p = tid & 3;
    float acc = 0.0f;
    for (int h = p; h < 16; h += 4) {
        const float4* q = (const float4*)&g_QL[(b * 16 + h) * 64];
        const float4* m = (const float4*)&bm[(((size_t)n * B_SZ + b) * H_N + h) * 64];
#pragma unroll
        for (int r4 = 0; r4 < 16; ++r4) {
            float4 qa = q[r4], ma = m[r4];
            acc += qa.x * ma.x + qa.y * ma.y + qa.z * ma.z + qa.w * ma.w;
        }
    }
    part[n][p] = acc;
    __syncthreads();
    if (tid < 64) {
        float v = part[tid][0] + part[tid][1] + part[tid][2] + part[tid][3];
        sarr[tid] = v * powf(GAMMA, (float)(NB - 1 - tid)) * (1.0f / 128.0f);
    }
    __syncthreads();
    if (tid == 0) {
        int i1 = 0; float v1 = sarr[0];
        for (int j = 1; j < 64; ++j) if (sarr[j] > v1) { v1 = sarr[j]; i1 = j; }
        int i2 = -1; float v2 = -INFINITY;
        for (int j = 0; j < 64; ++j) { if (j == i1) continue; if (sarr[j] > v2) { v2 = sarr[j]; i2 = j; } }
        si1 = i1; si2 = i2;
    }
    __syncthreads();

    int cur = curp[0];
    int i1 = si1, i2 = si2;
    int w0 = tid * 32;
    const int* br = bids + b * W_TOT;
    int c = 0;
    for (int j = 0; j < 32; ++j) {
        int id = br[w0 + j];
        if (id == i1 || id == i2 || id == cur) c++;
    }
    cnts[tid] = c;
    __syncthreads();
    if (tid == 0) {
        int t = 0;
        for (int k = 0; k < 256; ++k) { offs[k] = t; t += cnts[k]; }
        offs[256] = t;
        g_wcnt[b] = t;
    }
    __syncthreads();
    int o = offs[tid];
    for (int j = 0; j < 32; ++j) {
        int id = br[w0 + j];
        if (id == i1 || id == i2 || id == cur) g_widx[b * W_TOT + (o++)] = w0 + j;
    }
}

// ============================================================
// Kernel 5: masked softmax attention over routed list  grid=128, block=256
// ============================================================
__global__ void __launch_bounds__(256) k_attn(const float* __restrict__ Kl,
                                              const float* __restrict__ Vl) {
    int bh = blockIdx.x;
    int b = bh >> 4;
    int tid = threadIdx.x;

    __shared__ __align__(16) float QLs[64];
    __shared__ float logit[W_TOT];
    __shared__ float red[256];
    __shared__ float accv[4][64];
    __shared__ float s_max, s_sum;

    int nw = g_wcnt[b];
    if (tid < 64) QLs[tid] = g_QL[bh * 64 + tid];
    __syncthreads();

    const int* wl = g_widx + b * W_TOT;

    // pass 1: logits + local max
    float lm = -INFINITY;
    for (int i = tid; i < nw; i += 256) {
        int w = wl[i];
        const float4* kr = (const float4*)&Kl[((size_t)bh * W_TOT + w) * 64];
        const float4* qr = (const float4*)QLs;
        float d = 0.0f;
#pragma unroll
        for (int r4 = 0; r4 < 16; ++r4) {
            float4 kv = kr[r4], qv = qr[r4];
            d += kv.x * qv.x + kv.y * qv.y + kv.z * qv.z + kv.w * qv.w;
        }
        d *= 0.125f;   // 1/sqrt(64)
        logit[i] = d;
        lm = fmaxf(lm, d);
    }
    red[tid] = lm; __syncthreads();
    for (int o = 128; o; o >>= 1) { if (tid < o) red[tid] = fmaxf(red[tid], red[tid + o]); __syncthreads(); }
    if (tid == 0) s_max = red[0];
    __syncthreads();

    // pass 2: exp + sum
    float mx = s_max;
    float ls = 0.0f;
    for (int i = tid; i < nw; i += 256) {
        float e = expf(logit[i] - mx);
        logit[i] = e;
        ls += e;
    }
    red[tid] = ls; __syncthreads();
    for (int o = 128; o; o >>= 1) { if (tid < o) red[tid] += red[tid + o]; __syncthreads(); }
    if (tid == 0) s_sum = red[0];
    __syncthreads();

    // weighted V accumulation
    int r = tid & 63, g = tid >> 6;
    float acc = 0.0f;
    for (int i = g; i < nw; i += 4) {
        int w = wl[i];
        acc += logit[i] * Vl[((size_t)bh * W_TOT + w) * 64 + r];
    }
    accv[g][r] = acc;
    __syncthreads();
    if (tid < 64) {
        float a = (accv[0][tid] + accv[1][tid] + accv[2][tid] + accv[3][tid]) / s_sum;
        g_attn[bh * 64 + tid] = a;
    }
}

// ============================================================
// Kernel 6: fused tail (lin, skip-gate, gates, state update, output proj)
// grid=128 (b,h), block=256
// ============================================================
__global__ void __launch_bounds__(256) k_tail(
    const float* __restrict__ M, const float* __restrict__ z,
    const float* __restrict__ S_prev,
    const float* __restrict__ r1w, const float* __restrict__ r1b,
    const float* __restrict__ r2w, const float* __restrict__ r2b,
    const float* __restrict__ g1w, const float* __restrict__ g1b,
    const float* __restrict__ g2w, const float* __restrict__ g2b,
    const float* __restrict__ Ev, float* __restrict__ out) {

    int bh = blockIdx.x;
    int b = bh >> 4, h = bh & 15;
    int tid = threadIdx.x;

    __shared__ __align__(16) float Ms[4096];       // 16 KB
    __shared__ __align__(16) float u[256];         // [QL | KL | VL | attn]
    __shared__ __align__(16) float qf[64], zs[64], lin[64], errv[64], outlat[64];
    __shared__ __align__(16) float rh[128], gh[256], gout[192];
    __shared__ float partv[4][64];
    __shared__ float epartv[4][64];
    __shared__ float sc[8];  // 0:qz+eps 1:p_skip 2:alpha 3:eta 4:theta

    const float* Mg = M + (size_t)bh * 4096;
    for (int i = tid; i < 4096; i += 256) Ms[i] = Mg[i];
    if (tid < 64) {
        u[tid]       = g_QL[bh * 64 + tid];
        u[64 + tid]  = g_KL[bh * 64 + tid];
        u[128 + tid] = g_VL[bh * 64 + tid];
        u[192 + tid] = g_attn[bh * 64 + tid];
        zs[tid]      = z[bh * 64 + tid];
    }
    __syncthreads();

    // phase B: qf, rh, gh (all depend only on u)
    if (tid < 64) qf[tid] = softplusf(u[tid]);
    if (tid < 128) {
        const float4* wr = (const float4*)(r1w + tid * 64);
        const float4* qv = (const float4*)u;
        float a = r1b[tid];
#pragma unroll
        for (int k = 0; k < 16; ++k) {
            float4 wv = wr[k], uv = qv[k];
            a += wv.x * uv.x + wv.y * uv.y + wv.z * uv.z + wv.w * uv.w;
        }
        rh[tid] = geluf(a);
    }
    {
        const float4* wr = (const float4*)(g1w + (size_t)tid * 256);
        const float4* uv4 = (const float4*)u;
        float a = g1b[tid];
#pragma unroll
        for (int k = 0; k < 64; ++k) {
            float4 wv = wr[k], uv = uv4[k];
            a += wv.x * uv.x + wv.y * uv.y + wv.z * uv.z + wv.w * uv.w;
        }
        gh[tid] = geluf(a);
    }
    __syncthreads();

    // phase C: lin partials, err partials, gout
    {
        int s = tid & 63, g = tid >> 6;
        float a = 0.0f, e = 0.0f;
        for (int r = g; r < 64; r += 4) {
            float mrs = Ms[r * 64 + s];
            a += qf[r] * mrs;
            e += u[64 + r] * mrs;   // K_L @ M
        }
        partv[g][s] = a;
        epartv[g][s] = e;
    }
    if (tid < 192) {
        const float4* wr = (const float4*)(g2w + (size_t)tid * 256);
        const float4* gv4 = (const float4*)gh;
        float a = g2b[tid];
#pragma unroll
        for (int k = 0; k < 64; ++k) {
            float4 wv = wr[k], gv = gv4[k];
            a += wv.x * gv.x + wv.y * gv.y + wv.z * gv.z + wv.w * gv.w;
        }
        gout[tid] = a;
    }
    __syncthreads();

    // phase D: scalar reductions
    if (tid == 0) { float t = 0.0f; for (int k = 0; k < 64; ++k) t += qf[k] * zs[k]; sc[0] = t + 1e-6f; }
    if (tid == 1) { float t = r2b[0]; for (int k = 0; k < 128; ++k) t += rh[k] * r2w[k]; sc[1] = sigmoidf(t); }
    if (tid == 2) { float t = 0.0f; for (int k = 0; k < 64; ++k) t += gout[k]; sc[2] = sigmoidf(t * (1.0f / 64.0f)); }
    if (tid == 3) { float t = 0.0f; for (int k = 0; k < 64; ++k) t += gout[64 + k]; sc[3] = softplusf(t * (1.0f / 64.0f)); }
    if (tid == 4) { float t = 0.0f; for (int k = 0; k < 64; ++k) t += gout[128 + k]; sc[4] = softplusf(t * (1.0f / 64.0f)); }
    __syncthreads();

    // phase E: lin, err, out_lat, z_new
    if (tid < 64) {
        float l = (partv[0][tid] + partv[1][tid] + partv[2][tid] + partv[3][tid]) / sc[0];
        lin[tid] = l;
        errv[tid] = (epartv[0][tid] + epartv[1][tid] + epartv[2][tid] + epartv[3][tid]) - u[128 + tid];
        float ps = sc[1];
        outlat[tid] = (1.0f - ps) * u[192 + tid] + ps * l;
        float zn = (1.0f - sc[2]) * zs[tid] + softplusf(u[64 + tid]);
        out[Z_OFF + bh * 64 + tid] = zn;
    }
    __syncthreads();

    // phase F: state update (M_new, S_new) + output projection
    {
        float eta = sc[3], theta = sc[4], oma = 1.0f - sc[2];
        const float* Sg = S_prev + (size_t)bh * 4096;
        float* Mo = out + M_OFF + (size_t)bh * 4096;
        float* So = out + S_OFF + (size_t)bh * 4096;
        for (int idx = tid; idx < 4096; idx += 256) {
            int r = idx >> 6, s = idx & 63;
            float grad = u[64 + r] * errv[s];
            float sn = eta * Sg[idx] - theta * grad;
            So[idx] = sn;
            Mo[idx] = oma * Ms[idx] + sn;
        }
    }
    if (tid < 128) {
        const float4* er = (const float4*)(Ev + ((size_t)h * 128 + tid) * 64);
        const float4* ov = (const float4*)outlat;
        float a = 0.0f;
#pragma unroll
        for (int k = 0; k < 16; ++k) {
            float4 e = er[k], o = ov[k];
            a += e.x * o.x + e.y * o.y + e.z * o.z + e.w * o.w;
        }
        out[OUT_OFF + b * (H_N * D_V) + h * 128 + tid] = a;
    }
}

// ============================================================
extern "C" void kernel_launch(void* const* d_in, const int* in_sizes, int n_in,
                              void* d_out, int out_size) {
    const float* x     = (const float*)d_in[0];
    const float* ln_g  = (const float*)d_in[1];
    const float* ln_b  = (const float*)d_in[2];
    const float* W_qkv = (const float*)d_in[3];
    const float* E_q   = (const float*)d_in[4];
    const float* E_k   = (const float*)d_in[5];
    const float* E_v   = (const float*)d_in[6];
    const float* K_lat = (const float*)d_in[7];
    const float* V_lat = (const float*)d_in[8];
    const float* bm    = (const float*)d_in[9];
    const float* M     = (const float*)d_in[10];
    const float* z     = (const float*)d_in[11];
    const float* S_prev= (const float*)d_in[12];
    const float* r1w   = (const float*)d_in[13];
    const float* r1b   = (const float*)d_in[14];
    const float* r2w   = (const float*)d_in[15];
    const float* r2b   = (const float*)d_in[16];
    const float* g1w   = (const float*)d_in[17];
    const float* g1b   = (const float*)d_in[18];
    const float* g2w   = (const float*)d_in[19];
    const float* g2b   = (const float*)d_in[20];
    const int*   bids  = (const int*)d_in[21];
    const int*   cur   = (const int*)d_in[22];
    float* out = (float*)d_out;

    k_ln<<<B_SZ, 256>>>(x, ln_g, ln_b);
    k_qkv<<<QKV_COLS / 32, 256>>>(W_qkv);
    k_proj<<<B_SZ * H_N, 192>>>(E_q, E_k, E_v);
    k_route<<<B_SZ, 256>>>(bm, bids, cur);
    k_attn<<<B_SZ * H_N, 256>>>(K_lat, V_lat);
    k_tail<<<B_SZ * H_N, 256>>>(M, z, S_prev, r1w, r1b, r2w, r2b,
                                g1w, g1b, g2w, g2b, E_v, out);
}

// round 2
// speedup vs baseline: 1.2400x; 1.2400x over previous
#include <cuda_runtime.h>
#include <cuda_bf16.h>
#include <math.h>

// Problem constants
#define B_SZ 8
#define D_MODEL 2048
#define H_N 16
#define D_H 128
#define D_V 128
#define R_DIM 64
#define W_TOT 8192
#define NB 64
#define QKV_COLS (H_N * (2 * D_H + D_V))   // 6144

// Output layout (concatenated flat float32):
// out (8,2048) | M_new (8,16,64,64) | z_new (8,16,64) | S_new (8,16,64,64)
#define OUT_OFF 0
#define M_OFF   (B_SZ * H_N * D_V)                       // 16384
#define Z_OFF   (M_OFF + B_SZ * H_N * R_DIM * R_DIM)     // 540672
#define S_OFF   (Z_OFF + B_SZ * H_N * R_DIM)             // 548864

// -------- scratch (device globals; no allocation allowed) --------
__device__ __align__(16) float g_h[B_SZ * D_MODEL];
__device__ __align__(16) float g_qkv[B_SZ * QKV_COLS];
__device__ __align__(16) float g_QL[B_SZ * H_N * R_DIM];
__device__ __align__(16) float g_KL[B_SZ * H_N * R_DIM];
__device__ __align__(16) float g_VL[B_SZ * H_N * R_DIM];
__device__ __align__(16) float g_attn[B_SZ * H_N * R_DIM];
__device__ int g_widx[B_SZ * W_TOT];
__device__ int g_wcnt[B_SZ];

// -------- helpers --------
__device__ __forceinline__ float softplusf(float x) {
    return fmaxf(x, 0.0f) + log1pf(expf(-fabsf(x)));
}
__device__ __forceinline__ float geluf(float x) {
    return 0.5f * x * (1.0f + erff(x * 0.70710678118654752440f));
}
__device__ __forceinline__ float sigmoidf(float x) {
    return 1.0f / (1.0f + expf(-x));
}

// ============================================================
// Kernel 1: LayerNorm   grid=8, block=256
// ============================================================
__global__ void k_ln(const float* __restrict__ x,
                     const float* __restrict__ g,
                     const float* __restrict__ bb) {
    int b = blockIdx.x, tid = threadIdx.x;
    __shared__ float red[256];
    const float* xr = x + b * D_MODEL;

    float s = 0.0f;
    for (int i = tid; i < D_MODEL; i += 256) s += xr[i];
    red[tid] = s; __syncthreads();
    for (int o = 128; o; o >>= 1) { if (tid < o) red[tid] += red[tid + o]; __syncthreads(); }
    float mu = red[0] * (1.0f / D_MODEL);
    __syncthreads();

    float v = 0.0f;
    for (int i = tid; i < D_MODEL; i += 256) { float d = xr[i] - mu; v += d * d; }
    red[tid] = v; __syncthreads();
    for (int o = 128; o; o >>= 1) { if (tid < o) red[tid] += red[tid + o]; __syncthreads(); }
    float inv = 1.0f / sqrtf(red[0] * (1.0f / D_MODEL) + 1e-5f);

    for (int i = tid; i < D_MODEL; i += 256)
        g_h[b * D_MODEL + i] = (xr[i] - mu) * inv * g[i] + bb[i];
}

// ============================================================
// Kernel 2: qkv = h @ W_qkv^T   grid=192, block=256
// ============================================================
__global__ void __launch_bounds__(256) k_qkv(const float* __restrict__ W) {
    __shared__ float4 hs[B_SZ][128];   // 8 x 512 floats = 16 KB
    int tid = threadIdx.x;
    int warp = tid >> 5, lane = tid & 31;
    int colBase = blockIdx.x * 32 + warp * 4;

    float acc[4][8];
#pragma unroll
    for (int c = 0; c < 4; c++)
#pragma unroll
        for (int b = 0; b < 8; b++) acc[c][b] = 0.0f;

    for (int tile = 0; tile < 4; ++tile) {
        int k0 = tile * 512;
        for (int i = tid; i < 1024; i += 256) {
            int b = i >> 7, kk = i & 127;
            hs[b][kk] = *(const float4*)(&g_h[b * D_MODEL + k0 + kk * 4]);
        }
        __syncthreads();
#pragma unroll
        for (int kk = 0; kk < 4; ++kk) {
            int k4 = lane + kk * 32;
            float4 wv[4];
#pragma unroll
            for (int c = 0; c < 4; c++)
                wv[c] = *(const float4*)(&W[(size_t)(colBase + c) * D_MODEL + k0 + k4 * 4]);
#pragma unroll
            for (int b = 0; b < 8; b++) {
                float4 hv = hs[b][k4];
#pragma unroll
                for (int c = 0; c < 4; c++)
                    acc[c][b] += wv[c].x * hv.x + wv[c].y * hv.y + wv[c].z * hv.z + wv[c].w * hv.w;
            }
        }
        __syncthreads();
    }
#pragma unroll
    for (int c = 0; c < 4; c++)
#pragma unroll
        for (int b = 0; b < 8; b++) {
            float v = acc[c][b];
            for (int o = 16; o; o >>= 1) v += __shfl_down_sync(0xffffffffu, v, o);
            if (lane == 0) g_qkv[b * QKV_COLS + colBase + c] = v;
        }
}

// ============================================================
// Kernel 3: latent projections Q_L/K_L/V_L   grid=128, block=192
// ============================================================
__global__ void k_proj(const float* __restrict__ Eq,
                       const float* __restrict__ Ek,
                       const float* __restrict__ Ev) {
    int bh = blockIdx.x;
    int b = bh >> 4, h = bh & 15;
    int which = threadIdx.x / 64;
    int r = threadIdx.x & 63;

    const float* vec = g_qkv + b * QKV_COLS + h * 384 + which * 128;
    const float* E = (which == 0 ? Eq : (which == 1 ? Ek : Ev)) + (size_t)h * 128 * 64 + r;
    float acc = 0.0f;
#pragma unroll 8
    for (int d = 0; d < 128; ++d) acc += vec[d] * E[d * 64];

    float* dst = (which == 0 ? g_QL : (which == 1 ? g_KL : g_VL));
    dst[bh * 64 + r] = acc;
}

// ============================================================
// Kernel 4: routing scores + top-2 + UNORDERED compaction   grid=8, block=256
// Fully parallel: warp-shuffle argmax, atomic compaction, exp2f decay.
// ============================================================
__global__ void k_route(const float* __restrict__ bm,
                        const int* __restrict__ bids,
                        const int* __restrict__ curp) {
    int b = blockIdx.x, tid = threadIdx.x;
    __shared__ float part[64][4];
    __shared__ float sarr[64];
    __shared__ int s_i1, s_i2, s_cnt;

    int n = tid >> 2, p = tid & 3;
    float acc = 0.0f;
    for (int h = p; h < 16; h += 4) {
        const float4* q = (const float4*)&g_QL[(b * 16 + h) * 64];
        const float4* m = (const float4*)&bm[(((size_t)n * B_SZ + b) * H_N + h) * 64];
#pragma unroll
        for (int r4 = 0; r4 < 16; ++r4) {
            float4 qa = q[r4], ma = m[r4];
            acc += qa.x * ma.x + qa.y * ma.y + qa.z * ma.z + qa.w * ma.w;
        }
    }
    part[n][p] = acc;
    if (tid == 0) s_cnt = 0;
    __syncthreads();
    if (tid < 64) {
        float v = part[tid][0] + part[tid][1] + part[tid][2] + part[tid][3];
        // gamma^(63-n) / (sqrt(R)*H) ;  log2(0.97) = -0.04394335
        sarr[tid] = v * exp2f((float)(63 - tid) * -0.04394335f) * 0.0078125f;
    }
    __syncthreads();

    if (tid < 32) {
        // top-1 over 64 (lower index wins ties, matching lax.top_k)
        float v0 = sarr[tid], v1 = sarr[tid + 32];
        float bv; int bi;
        if (v0 >= v1) { bv = v0; bi = tid; } else { bv = v1; bi = tid + 32; }
#pragma unroll
        for (int o = 16; o; o >>= 1) {
            float ov = __shfl_down_sync(0xffffffffu, bv, o);
            int   oi = __shfl_down_sync(0xffffffffu, bi, o);
            if (ov > bv || (ov == bv && oi < bi)) { bv = ov; bi = oi; }
        }
        int i1 = __shfl_sync(0xffffffffu, bi, 0);
        // top-2: exclude i1
        float w0 = (tid == i1)      ? -INFINITY : sarr[tid];
        float w1 = (tid + 32 == i1) ? -INFINITY : sarr[tid + 32];
        float cv; int ci;
        if (w0 >= w1) { cv = w0; ci = tid; } else { cv = w1; ci = tid + 32; }
#pragma unroll
        for (int o = 16; o; o >>= 1) {
            float ov = __shfl_down_sync(0xffffffffu, cv, o);
            int   oi = __shfl_down_sync(0xffffffffu, ci, o);
            if (ov > cv || (ov == cv && oi < ci)) { cv = ov; ci = oi; }
        }
        if (tid == 0) { s_i1 = i1; s_i2 = ci; }
    }
    __syncthreads();

    int cur = curp[0];
    int i1 = s_i1, i2 = s_i2;
    const int* br = bids + b * W_TOT;
    for (int w = tid; w < W_TOT; w += 256) {
        int id = br[w];
        if (id == i1 || id == i2 || id == cur) {
            int pos = atomicAdd(&s_cnt, 1);
            g_widx[b * W_TOT + pos] = w;
        }
    }
    __syncthreads();
    if (tid == 0) g_wcnt[b] = s_cnt;
}

// ============================================================
// Kernel 5: masked softmax attention over routed list  grid=128, block=256
// ============================================================
__global__ void __launch_bounds__(256) k_attn(const float* __restrict__ Kl,
                                              const float* __restrict__ Vl) {
    int bh = blockIdx.x;
    int b = bh >> 4;
    int tid = threadIdx.x;

    __shared__ __align__(16) float QLs[64];
    __shared__ float logit[W_TOT];
    __shared__ float red[256];
    __shared__ __align__(16) float accv[16][64];
    __shared__ float s_max, s_sum;

    int nw = g_wcnt[b];
    if (tid < 64) QLs[tid] = g_QL[bh * 64 + tid];
    __syncthreads();

    const int* wl = g_widx + b * W_TOT;

    // pass 1: logits + local max
    float lm = -INFINITY;
    for (int i = tid; i < nw; i += 256) {
        int w = wl[i];
        const float4* kr = (const float4*)&Kl[((size_t)bh * W_TOT + w) * 64];
        const float4* qr = (const float4*)QLs;
        float d = 0.0f;
#pragma unroll
        for (int r4 = 0; r4 < 16; ++r4) {
            float4 kv = kr[r4], qv = qr[r4];
            d += kv.x * qv.x + kv.y * qv.y + kv.z * qv.z + kv.w * qv.w;
        }
        d *= 0.125f;   // 1/sqrt(64)
        logit[i] = d;
        lm = fmaxf(lm, d);
    }
    red[tid] = lm; __syncthreads();
    for (int o = 128; o; o >>= 1) { if (tid < o) red[tid] = fmaxf(red[tid], red[tid + o]); __syncthreads(); }
    if (tid == 0) s_max = red[0];
    __syncthreads();

    // pass 2: exp + sum
    float mx = s_max;
    float ls = 0.0f;
    for (int i = tid; i < nw; i += 256) {
        float e = expf(logit[i] - mx);
        logit[i] = e;
        ls += e;
    }
    red[tid] = ls; __syncthreads();
    for (int o = 128; o; o >>= 1) { if (tid < o) red[tid] += red[tid + o]; __syncthreads(); }
    if (tid == 0) s_sum = red[0];
    __syncthreads();

    // weighted V accumulation, float4-vectorized
    int r4 = tid & 15, g = tid >> 4;
    float4 a4 = make_float4(0.0f, 0.0f, 0.0f, 0.0f);
    for (int i = g; i < nw; i += 16) {
        int w = wl[i];
        float pw = logit[i];
        float4 v = *(const float4*)&Vl[((size_t)bh * W_TOT + w) * 64 + r4 * 4];
        a4.x += pw * v.x; a4.y += pw * v.y; a4.z += pw * v.z; a4.w += pw * v.w;
    }
    *(float4*)&accv[g][r4 * 4] = a4;
    __syncthreads();
    if (tid < 64) {
        float a = 0.0f;
#pragma unroll
        for (int gg = 0; gg < 16; ++gg) a += accv[gg][tid];
        g_attn[bh * 64 + tid] = a / s_sum;
    }
}

// ============================================================
// Kernel 6: fused tail   grid=128 (b,h), block=256
// ============================================================
__global__ void __launch_bounds__(256) k_tail(
    const float* __restrict__ M, const float* __restrict__ z,
    const float* __restrict__ S_prev,
    const float* __restrict__ r1w, const float* __restrict__ r1b,
    const float* __restrict__ r2w, const float* __restrict__ r2b,
    const float* __restrict__ g1w, const float* __restrict__ g1b,
    const float* __restrict__ g2w, const float* __restrict__ g2b,
    const float* __restrict__ Ev, float* __restrict__ out) {

    int bh = blockIdx.x;
    int b = bh >> 4, h = bh & 15;
    int tid = threadIdx.x;

    __shared__ __align__(16) float Ms[4096];       // 16 KB
    __shared__ __align__(16) float u[256];         // [QL | KL | VL | attn]
    __shared__ __align__(16) float qf[64], zs[64], lin[64], errv[64], outlat[64];
    __shared__ __align__(16) float rh[128], gh[256], gout[192];
    __shared__ float partv[4][64];
    __shared__ float epartv[4][64];
    __shared__ float sc[8];  // 0:qz+eps 1:p_skip 2:alpha 3:eta 4:theta

    const float4* Mg4 = (const float4*)(M + (size_t)bh * 4096);
    float4* Ms4 = (float4*)Ms;
    for (int i = tid; i < 1024; i += 256) Ms4[i] = Mg4[i];
    if (tid < 64) {
        u[tid]       = g_QL[bh * 64 + tid];
        u[64 + tid]  = g_KL[bh * 64 + tid];
        u[128 + tid] = g_VL[bh * 64 + tid];
        u[192 + tid] = g_attn[bh * 64 + tid];
        zs[tid]      = z[bh * 64 + tid];
    }
    __syncthreads();

    // phase B: qf, rh, gh
    if (tid < 64) qf[tid] = softplusf(u[tid]);
    if (tid < 128) {
        const float4* wr = (const float4*)(r1w + tid * 64);
        const float4* qv = (const float4*)u;
        float a = r1b[tid];
#pragma unroll
        for (int k = 0; k < 16; ++k) {
            float4 wv = wr[k], uv = qv[k];
            a += wv.x * uv.x + wv.y * uv.y + wv.z * uv.z + wv.w * uv.w;
        }
        rh[tid] = geluf(a);
    }
    {
        const float4* wr = (const float4*)(g1w + (size_t)tid * 256);
        const float4* uv4 = (const float4*)u;
        float a = g1b[tid];
#pragma unroll
        for (int k = 0; k < 64; ++k) {
            float4 wv = wr[k], uv = uv4[k];
            a += wv.x * uv.x + wv.y * uv.y + wv.z * uv.z + wv.w * uv.w;
        }
        gh[tid] = geluf(a);
    }
    __syncthreads();

    // phase C: lin partials, err partials, gout
    {
        int s = tid & 63, g = tid >> 6;
        float a = 0.0f, e = 0.0f;
        for (int r = g; r < 64; r += 4) {
            float mrs = Ms[r * 64 + s];
            a += qf[r] * mrs;
            e += u[64 + r] * mrs;   // K_L @ M
        }
        partv[g][s] = a;
        epartv[g][s] = e;
    }
    if (tid < 192) {
        const float4* wr = (const float4*)(g2w + (size_t)tid * 256);
        const float4* gv4 = (const float4*)gh;
        float a = g2b[tid];
#pragma unroll
        for (int k = 0; k < 64; ++k) {
            float4 wv = wr[k], gv = gv4[k];
            a += wv.x * gv.x + wv.y * gv.y + wv.z * gv.z + wv.w * gv.w;
        }
        gout[tid] = a;
    }
    __syncthreads();

    // phase D: scalar reductions
    if (tid == 0) { float t = 0.0f; for (int k = 0; k < 64; ++k) t += qf[k] * zs[k]; sc[0] = t + 1e-6f; }
    if (tid == 1) { float t = r2b[0]; for (int k = 0; k < 128; ++k) t += rh[k] * r2w[k]; sc[1] = sigmoidf(t); }
    if (tid == 2) { float t = 0.0f; for (int k = 0; k < 64; ++k) t += gout[k]; sc[2] = sigmoidf(t * (1.0f / 64.0f)); }
    if (tid == 3) { float t = 0.0f; for (int k = 0; k < 64; ++k) t += gout[64 + k]; sc[3] = softplusf(t * (1.0f / 64.0f)); }
    if (tid == 4) { float t = 0.0f; for (int k = 0; k < 64; ++k) t += gout[128 + k]; sc[4] = softplusf(t * (1.0f / 64.0f)); }
    __syncthreads();

    // phase E: lin, err, out_lat, z_new
    if (tid < 64) {
        float l = (partv[0][tid] + partv[1][tid] + partv[2][tid] + partv[3][tid]) / sc[0];
        lin[tid] = l;
        errv[tid] = (epartv[0][tid] + epartv[1][tid] + epartv[2][tid] + epartv[3][tid]) - u[128 + tid];
        float ps = sc[1];
        outlat[tid] = (1.0f - ps) * u[192 + tid] + ps * l;
        float zn = (1.0f - sc[2]) * zs[tid] + softplusf(u[64 + tid]);
        out[Z_OFF + bh * 64 + tid] = zn;
    }
    __syncthreads();

    // phase F: state update (M_new, S_new) + output projection, float4
    {
        float eta = sc[3], theta = sc[4], oma = 1.0f - sc[2];
        const float4* Sg4 = (const float4*)(S_prev + (size_t)bh * 4096);
        float4* Mo4 = (float4*)(out + M_OFF + (size_t)bh * 4096);
        float4* So4 = (float4*)(out + S_OFF + (size_t)bh * 4096);
        const float4* ev4 = (const float4*)errv;
        for (int idx = tid; idx < 1024; idx += 256) {
            int r = idx >> 4, s4 = idx & 15;
            float kl = u[64 + r];
            float4 e = ev4[s4];
            float4 sg = Sg4[idx];
            float4 ms = Ms4[idx];
            float4 sn;
            sn.x = eta * sg.x - theta * (kl * e.x);
            sn.y = eta * sg.y - theta * (kl * e.y);
            sn.z = eta * sg.z - theta * (kl * e.z);
            sn.w = eta * sg.w - theta * (kl * e.w);
            So4[idx] = sn;
            float4 mn;
            mn.x = oma * ms.x + sn.x;
            mn.y = oma * ms.y + sn.y;
            mn.z = oma * ms.z + sn.z;
            mn.w = oma * ms.w + sn.w;
            Mo4[idx] = mn;
        }
    }
    if (tid < 128) {
        const float4* er = (const float4*)(Ev + ((size_t)h * 128 + tid) * 64);
        const float4* ov = (const float4*)outlat;
        float a = 0.0f;
#pragma unroll
        for (int k = 0; k < 16; ++k) {
            float4 e = er[k], o = ov[k];
            a += e.x * o.x + e.y * o.y + e.z * o.z + e.w * o.w;
        }
        out[OUT_OFF + b * (H_N * D_V) + h * 128 + tid] = a;
    }
}

// ============================================================
extern "C" void kernel_launch(void* const* d_in, const int* in_sizes, int n_in,
                              void* d_out, int out_size) {
    const float* x     = (const float*)d_in[0];
    const float* ln_g  = (const float*)d_in[1];
    const float* ln_b  = (const float*)d_in[2];
    const float* W_qkv = (const float*)d_in[3];
    const float* E_q   = (const float*)d_in[4];
    const float* E_k   = (const float*)d_in[5];
    const float* E_v   = (const float*)d_in[6];
    const float* K_lat = (const float*)d_in[7];
    const float* V_lat = (const float*)d_in[8];
    const float* bm    = (const float*)d_in[9];
    const float* M     = (const float*)d_in[10];
    const float* z     = (const float*)d_in[11];
    const float* S_prev= (const float*)d_in[12];
    const float* r1w   = (const float*)d_in[13];
    const float* r1b   = (const float*)d_in[14];
    const float* r2w   = (const float*)d_in[15];
    const float* r2b   = (const float*)d_in[16];
    const float* g1w   = (const float*)d_in[17];
    const float* g1b   = (const float*)d_in[18];
    const float* g2w   = (const float*)d_in[19];
    const float* g2b   = (const float*)d_in[20];
    const int*   bids  = (const int*)d_in[21];
    const int*   cur   = (const int*)d_in[22];
    float* out = (float*)d_out;

    k_ln<<<B_SZ, 256>>>(x, ln_g, ln_b);
    k_qkv<<<QKV_COLS / 32, 256>>>(W_qkv);
    k_proj<<<B_SZ * H_N, 192>>>(E_q, E_k, E_v);
    k_route<<<B_SZ, 256>>>(bm, bids, cur);
    k_attn<<<B_SZ * H_N, 256>>>(K_lat, V_lat);
    k_tail<<<B_SZ * H_N, 256>>>(M, z, S_prev, r1w, r1b, r2w, r2b,
                                g1w, g1b, g2w, g2b, E_v, out);
}